// round 1
// baseline (speedup 1.0000x reference)
#include <cuda_runtime.h>

constexpr int LDIM = 384;
constexpr int NHW  = 147456;   // 384*384
constexpr int CH   = 64;
constexpr int ND1  = 788;
constexpr int ND2  = 210;
#define EPSV 1e-5f

// ---------------- device scratch (static, no allocations) ----------------
__device__ float g_bufT[CH*NHW];
__device__ float g_bufU[CH*NHW];
__device__ float g_bufX[CH*NHW];
__device__ float g_rs1[ND1];
__device__ float g_rs2[ND2];
__device__ float g_W1af[CH*ND1];
__device__ float g_W1bf[CH*ND1];
__device__ float g_W2f[CH*ND2];
__device__ float g_row[CH*LDIM];
__device__ float g_col[CH*LDIM];
__device__ float g_a1[CH], g_c1[CH], g_a2[CH], g_c2[CH];
__device__ float g_aG[CH], g_cG[CH];
__device__ float g_accS[ND2], g_accQ[ND2];
__device__ float g_wT[10*CH*9*CH];   // transposed conv weights [lk][ci][tap][co]

__device__ __forceinline__ float lrelu(float v){ return fmaxf(v, 0.01f*v); }

__device__ __forceinline__ float wsum(float v){
  #pragma unroll
  for(int o=16;o>0;o>>=1) v += __shfl_down_sync(0xffffffffu, v, o);
  return v;
}

// ---------------- small kernels ----------------
__global__ void k_zero(){
  int t = threadIdx.x;
  if(t < ND2){ g_accS[t]=0.f; g_accQ[t]=0.f; }
}

__global__ void k_prepW(const float* __restrict__ rw){
  int idx = blockIdx.x*256 + threadIdx.x;
  if(idx < 10*CH*9*CH){
    int lk  = idx / (CH*9*CH);
    int rem = idx % (CH*9*CH);
    int ci  = rem / (9*CH);
    int r2  = rem % (9*CH);
    int kk  = r2 / CH;
    int co  = r2 % CH;
    // rw layout: [lk][co][ci][ky][kx]
    g_wT[idx] = rw[ ((lk*CH + co)*CH + ci)*9 + kk ];
  }
}

__global__ void k_stats1d(const float* __restrict__ x1){
  int d = blockIdx.x;
  const float* p = x1 + d*LDIM;
  float s=0.f,q=0.f;
  for(int i=threadIdx.x;i<LDIM;i+=128){ float v=p[i]; s+=v; q+=v*v; }
  __shared__ float ss[4], sq[4];
  s = wsum(s); q = wsum(q);
  int w = threadIdx.x>>5, ln = threadIdx.x&31;
  if(ln==0){ ss[w]=s; sq[w]=q; }
  __syncthreads();
  if(threadIdx.x==0){
    float S=ss[0]+ss[1]+ss[2]+ss[3], Q=sq[0]+sq[1]+sq[2]+sq[3];
    float mu=S/(float)LDIM; float var=Q/(float)LDIM-mu*mu;
    g_rs1[d]=rsqrtf(var+EPSV);
  }
}

__global__ void k_stats2(const float* __restrict__ x2){
  int d = blockIdx.x, seg = blockIdx.y;
  const float* p = x2 + d*NHW + seg*36864;
  float s=0.f,q=0.f;
  for(int i=threadIdx.x;i<36864;i+=256){ float v=p[i]; s+=v; q+=v*v; }
  __shared__ float ss[8], sq[8];
  s=wsum(s); q=wsum(q);
  int w=threadIdx.x>>5, ln=threadIdx.x&31;
  if(ln==0){ ss[w]=s; sq[w]=q; }
  __syncthreads();
  if(threadIdx.x==0){
    float S=0.f,Q=0.f;
    #pragma unroll
    for(int i=0;i<8;i++){S+=ss[i];Q+=sq[i];}
    atomicAdd(&g_accS[d],S); atomicAdd(&g_accQ[d],Q);
  }
}

__global__ void k_fin_rs2(){
  int t=threadIdx.x;
  if(t<ND2){
    float mu = g_accS[t]/(float)NHW;
    float var = g_accQ[t]/(float)NHW - mu*mu;
    g_rs2[t] = rsqrtf(var+EPSV);
  }
}

__global__ void k_foldW1(const float* __restrict__ W1){
  int idx = blockIdx.x*256+threadIdx.x;
  if(idx < CH*ND1){
    int c = idx/ND1, d = idx%ND1;
    float rs = g_rs1[d];
    g_W1af[idx] = W1[c*2*ND1 + d]*rs;
    g_W1bf[idx] = W1[c*2*ND1 + ND1 + d]*rs;
  }
}

__global__ void k_foldW2(const float* __restrict__ W2){
  int idx = blockIdx.x*256+threadIdx.x;
  if(idx < CH*ND2) g_W2f[idx] = W2[idx]*g_rs2[idx%ND2];
}

__global__ void k_rowcol(const float* __restrict__ x1){
  int c = blockIdx.x, i = threadIdx.x;
  const float* wa = g_W1af + c*ND1;
  const float* wb = g_W1bf + c*ND1;
  float r=0.f, cl=0.f;
  for(int d=0; d<ND1; d++){
    float v = x1[d*LDIM + i];
    r  += wa[d]*v;
    cl += wb[d]*v;
  }
  g_row[c*LDIM+i]=r; g_col[c*LDIM+i]=cl;
}

__global__ void k_rcstats(const float* __restrict__ g1, const float* __restrict__ b1){
  int c = blockIdx.x;
  float sr=0.f,qr=0.f,sc=0.f,qc=0.f;
  for(int i=threadIdx.x;i<LDIM;i+=128){
    float r=g_row[c*LDIM+i], cl=g_col[c*LDIM+i];
    sr+=r; qr+=r*r; sc+=cl; qc+=cl*cl;
  }
  __shared__ float sm4[4][4];
  sr=wsum(sr); qr=wsum(qr); sc=wsum(sc); qc=wsum(qc);
  int w=threadIdx.x>>5, ln=threadIdx.x&31;
  if(ln==0){ sm4[w][0]=sr; sm4[w][1]=qr; sm4[w][2]=sc; sm4[w][3]=qc; }
  __syncthreads();
  if(threadIdx.x==0){
    float Sr=0.f,Qr=0.f,Sc=0.f,Qc=0.f;
    #pragma unroll
    for(int i=0;i<4;i++){Sr+=sm4[i][0];Qr+=sm4[i][1];Sc+=sm4[i][2];Qc+=sm4[i][3];}
    float mr=Sr/(float)LDIM, mc=Sc/(float)LDIM;
    float vr=Qr/(float)LDIM-mr*mr, vc=Qc/(float)LDIM-mc*mc;
    float rs=rsqrtf(vr+vc+EPSV);
    float a=g1[c]*rs;
    g_a1[c]=a; g_c1[c]=b1[c]-(mr+mc)*a;
  }
}

// pair2 GEMM: y2[c,p] = sum_d W2f[c,d] * x2[d,p]   (mean folded out — cancels in inorm)
__global__ void k_pair2(const float* __restrict__ x2){
  extern __shared__ float sm[];
  float* W2s = sm;           // CH*ND2
  float* xs  = sm + CH*ND2;  // 6*128
  int tid=threadIdx.x;
  for(int i=tid;i<CH*ND2;i+=256) W2s[i]=g_W2f[i];
  int px = tid & 127, cg = tid >> 7;
  int pix0 = blockIdx.x*128;
  float acc[32];
  #pragma unroll
  for(int k=0;k<32;k++) acc[k]=0.f;
  __syncthreads();
  for(int d0=0; d0<ND2; d0+=6){
    for(int i=tid;i<6*128;i+=256) xs[i] = x2[(d0 + (i>>7))*NHW + pix0 + (i&127)];
    __syncthreads();
    #pragma unroll
    for(int dd=0;dd<6;dd++){
      float v = xs[dd*128+px];
      const float* wp = W2s + (cg*32)*ND2 + d0 + dd;
      #pragma unroll
      for(int k=0;k<32;k++) acc[k] += wp[k*ND2]*v;
    }
    __syncthreads();
  }
  #pragma unroll
  for(int k=0;k<32;k++) g_bufU[(cg*32+k)*NHW + pix0+px] = acc[k];
}

// pair stage: p1 act (separable) + p2 act, then 64x128 channel mix into bufX
__global__ void k_pair(const float* __restrict__ W3){
  extern __shared__ float sm[];
  float* Wa  = sm;            // 64*64
  float* Wb  = sm+4096;       // 64*64
  float* p1s = sm+8192;       // 64*32 [c][px]
  float* p2s = sm+8192+2048;  // 64*32
  int tid=threadIdx.x;
  for(int i=tid;i<4096;i+=256){
    int c=i>>6, d=i&63;
    Wa[i]=W3[c*128+d]; Wb[i]=W3[c*128+64+d];
  }
  int px=tid&31, cg=tid>>5;
  int P = blockIdx.x*32 + px;
  int i = P/LDIM, j = P - i*LDIM;
  __syncthreads();
  #pragma unroll
  for(int r=0;r<8;r++){
    int c=cg*8+r;
    float v1 = g_row[c*LDIM+i] + g_col[c*LDIM+j];
    p1s[c*32+px] = lrelu(g_a1[c]*v1 + g_c1[c]);
    float u = g_bufU[c*NHW + P];
    p2s[c*32+px] = lrelu(g_a2[c]*u + g_c2[c]);
  }
  __syncthreads();
  float acc[8];
  #pragma unroll
  for(int r=0;r<8;r++) acc[r]=0.f;
  for(int dd=0;dd<64;dd++){
    float v1=p1s[dd*32+px], v2=p2s[dd*32+px];
    #pragma unroll
    for(int r=0;r<8;r++){
      int c=cg*8+r;
      acc[r] += Wa[c*64+dd]*v1 + Wb[c*64+dd]*v2;
    }
  }
  #pragma unroll
  for(int r=0;r<8;r++) g_bufX[(cg*8+r)*NHW + P] = acc[r];
}

__global__ void k_cstats(const float* __restrict__ buf){
  int c=blockIdx.x, seg=blockIdx.y;
  const float* p = buf + c*NHW + seg*18432;
  float s=0.f,q=0.f;
  for(int i=threadIdx.x;i<18432;i+=256){ float v=p[i]; s+=v; q+=v*v; }
  __shared__ float ss[8], sq[8];
  s=wsum(s); q=wsum(q);
  int w=threadIdx.x>>5, ln=threadIdx.x&31;
  if(ln==0){ ss[w]=s; sq[w]=q; }
  __syncthreads();
  if(threadIdx.x==0){
    float S=0.f,Q=0.f;
    #pragma unroll
    for(int i=0;i<8;i++){S+=ss[i];Q+=sq[i];}
    atomicAdd(&g_accS[c],S); atomicAdd(&g_accQ[c],Q);
  }
}

__global__ void k_fin_affine(const float* __restrict__ gamma, const float* __restrict__ beta,
                             float* __restrict__ aOut, float* __restrict__ cOut){
  int t=threadIdx.x;
  if(t<CH){
    float mu = g_accS[t]/(float)NHW;
    float var = g_accQ[t]/(float)NHW - mu*mu;
    float rs = rsqrtf(var+EPSV);
    float a = gamma[t]*rs;
    aOut[t]=a; cOut[t]=beta[t]-mu*a;
  }
}

__global__ void k_apply(float* __restrict__ buf){
  int c=blockIdx.y;
  int idx=c*NHW + blockIdx.x*256 + threadIdx.x;
  buf[idx] = lrelu(g_aG[c]*buf[idx]+g_cG[c]);
}

__global__ void k_apply_res(const float* __restrict__ u, const float* __restrict__ res,
                            float* __restrict__ o){
  int c=blockIdx.y;
  int idx=c*NHW + blockIdx.x*256 + threadIdx.x;
  o[idx] = lrelu(g_aG[c]*u[idx]+g_cG[c]) + res[idx];
}

// ---------------- conv 3x3 dilated, 64->64, packed f32x2 ----------------
template<int D>
__global__ void k_conv(const float* __restrict__ in, float* __restrict__ out,
                       const float* __restrict__ wT){
  extern __shared__ float smx[];
  float* ws = smx;                  // 64*9*64 floats = 147456 B, [ci][tap][co]
  const int TW = 16 + 2*D;
  float* tile = smx + CH*9*CH;      // 4 * TW*TW
  int tid = threadIdx.x;

  // stage weights (coalesced float4)
  {
    const float4* wg = (const float4*)wT;
    float4* ws4 = (float4*)ws;
    for(int i=tid;i<(CH*9*CH)/4;i+=256) ws4[i]=wg[i];
  }
  int px = tid & 15, py = tid >> 4;
  int gx0 = blockIdx.x*16 - D, gy0 = blockIdx.y*16 - D;

  unsigned long long acc[32];
  #pragma unroll
  for(int p=0;p<32;p++) acc[p]=0ULL;   // {0.f, 0.f}

  for(int c0=0;c0<CH;c0+=4){
    __syncthreads();   // weights ready (first iter) / previous tile consumed
    for(int i=tid;i<4*TW*TW;i+=256){
      int cc=i/(TW*TW); int r=i%(TW*TW); int ty=r/TW, tx=r%TW;
      int gy=gy0+ty, gx=gx0+tx;
      float v = 0.f;
      if(gy>=0 && gy<LDIM && gx>=0 && gx<LDIM) v = in[(c0+cc)*NHW + gy*LDIM + gx];
      tile[i]=v;
    }
    __syncthreads();
    #pragma unroll
    for(int cc=0;cc<4;cc++){
      int ci=c0+cc;
      const float* tp = tile + cc*TW*TW + py*TW + px;
      const ulonglong2* wrow = ((const ulonglong2*)ws) + ci*9*16;
      #pragma unroll
      for(int kk=0;kk<9;kk++){
        int ky=kk/3, kx=kk%3;
        float v = tp[ky*D*TW + kx*D];
        unsigned long long vd;
        asm("mov.b64 %0, {%1,%1};" : "=l"(vd) : "f"(v));
        const ulonglong2* wk = wrow + kk*16;
        #pragma unroll
        for(int p=0;p<16;p++){
          ulonglong2 w2 = wk[p];
          asm("fma.rn.f32x2 %0, %1, %2, %0;" : "+l"(acc[2*p  ]) : "l"(w2.x), "l"(vd));
          asm("fma.rn.f32x2 %0, %1, %2, %0;" : "+l"(acc[2*p+1]) : "l"(w2.y), "l"(vd));
        }
      }
    }
  }
  int gy = blockIdx.y*16+py, gx = blockIdx.x*16+px;
  int base = gy*LDIM+gx;
  #pragma unroll
  for(int p=0;p<32;p++){
    float lo,hi;
    asm("mov.b64 {%0,%1}, %2;" : "=f"(lo), "=f"(hi) : "l"(acc[p]));
    out[(2*p  )*NHW+base]=lo;
    out[(2*p+1)*NHW+base]=hi;
  }
}

// ---------------- host ----------------
static void launch_conv(int d, const float* in, float* out, const float* w){
  dim3 g(24,24);
  if(d==1)      k_conv<1><<<g,256,152640>>>(in,out,w);
  else if(d==2) k_conv<2><<<g,256,153856>>>(in,out,w);
  else          k_conv<4><<<g,256,156672>>>(in,out,w);
}

extern "C" void kernel_launch(void* const* d_in, const int* in_sizes, int n_in,
                              void* d_out, int out_size){
  const float* x1 =(const float*)d_in[0];
  const float* x2 =(const float*)d_in[1];
  const float* W1 =(const float*)d_in[2];
  const float* g1 =(const float*)d_in[3];
  const float* b1 =(const float*)d_in[4];
  const float* W2 =(const float*)d_in[5];
  const float* g2 =(const float*)d_in[6];
  const float* b2 =(const float*)d_in[7];
  const float* W3 =(const float*)d_in[8];
  const float* g3 =(const float*)d_in[9];
  const float* b3 =(const float*)d_in[10];
  const float* rw =(const float*)d_in[11];
  const float* rg =(const float*)d_in[13];
  const float* rbe=(const float*)d_in[14];
  float* outp=(float*)d_out;

  float *bufT,*bufU,*bufX,*wT,*a2p,*c2p,*aGp,*cGp;
  cudaGetSymbolAddress((void**)&bufT, g_bufT);
  cudaGetSymbolAddress((void**)&bufU, g_bufU);
  cudaGetSymbolAddress((void**)&bufX, g_bufX);
  cudaGetSymbolAddress((void**)&wT,   g_wT);
  cudaGetSymbolAddress((void**)&a2p,  g_a2);
  cudaGetSymbolAddress((void**)&c2p,  g_c2);
  cudaGetSymbolAddress((void**)&aGp,  g_aG);
  cudaGetSymbolAddress((void**)&cGp,  g_cG);

  cudaFuncSetAttribute(k_conv<1>, cudaFuncAttributeMaxDynamicSharedMemorySize, 152640);
  cudaFuncSetAttribute(k_conv<2>, cudaFuncAttributeMaxDynamicSharedMemorySize, 153856);
  cudaFuncSetAttribute(k_conv<4>, cudaFuncAttributeMaxDynamicSharedMemorySize, 156672);
  cudaFuncSetAttribute(k_pair2,   cudaFuncAttributeMaxDynamicSharedMemorySize, 56832);
  cudaFuncSetAttribute(k_pair,    cudaFuncAttributeMaxDynamicSharedMemorySize, 49152);

  k_prepW<<<(10*CH*9*CH+255)/256,256>>>(rw);
  k_zero<<<1,256>>>();
  k_stats1d<<<788,128>>>(x1);
  k_stats2<<<dim3(210,4),256>>>(x2);
  k_fin_rs2<<<1,256>>>();
  k_foldW1<<<(CH*ND1+255)/256,256>>>(W1);
  k_foldW2<<<(CH*ND2+255)/256,256>>>(W2);
  k_rowcol<<<64,384>>>(x1);
  k_rcstats<<<64,128>>>(g1,b1);
  k_pair2<<<1152,256,56832>>>(x2);
  k_zero<<<1,256>>>();
  k_cstats<<<dim3(64,8),256>>>(bufU);
  k_fin_affine<<<1,64>>>(g2,b2,a2p,c2p);
  k_pair<<<4608,256,49152>>>(W3);
  k_zero<<<1,256>>>();
  k_cstats<<<dim3(64,8),256>>>(bufX);
  k_fin_affine<<<1,64>>>(g3,b3,aGp,cGp);
  k_apply<<<dim3(576,64),256>>>(bufX);

  const int dil[5]={1,2,4,2,1};
  for(int l=0;l<5;l++){
    int d=dil[l];
    const float* w0 = wT + (l*2  )*(CH*9*CH);
    const float* w1 = wT + (l*2+1)*(CH*9*CH);
    launch_conv(d, bufX, bufT, w0);
    k_zero<<<1,256>>>();
    k_cstats<<<dim3(64,8),256>>>(bufT);
    k_fin_affine<<<1,64>>>(rg + (l*2)*CH, rbe + (l*2)*CH, aGp, cGp);
    k_apply<<<dim3(576,64),256>>>(bufT);
    launch_conv(d, bufT, bufU, w1);
    k_zero<<<1,256>>>();
    k_cstats<<<dim3(64,8),256>>>(bufU);
    k_fin_affine<<<1,64>>>(rg + (l*2+1)*CH, rbe + (l*2+1)*CH, aGp, cGp);
    k_apply_res<<<dim3(576,64),256>>>(bufU, bufX, (l==4)? outp : bufX);
  }
}

// round 3
// speedup vs baseline: 1.6262x; 1.6262x over previous
#include <cuda_runtime.h>
#include <cstdint>

constexpr int LDIM = 384;
constexpr int NHW  = 147456;   // 384*384
constexpr int CH   = 64;
constexpr int ND1  = 788;
constexpr int ND2  = 210;
#define EPSV 1e-5f

// ---------------- device scratch (static, no allocations) ----------------
__device__ float g_bufT[CH*NHW];
__device__ float g_bufU[CH*NHW];
__device__ float g_bufX[CH*NHW];
__device__ float g_rs1[ND1];
__device__ float g_rs2[ND2];
__device__ float g_W1af[CH*ND1];
__device__ float g_W1bf[CH*ND1];
__device__ float g_W2f[CH*ND2];
__device__ float g_row[CH*LDIM];
__device__ float g_col[CH*LDIM];
__device__ float g_a1[CH], g_c1[CH], g_a2[CH], g_c2[CH];
__device__ float g_aG[CH], g_cG[CH];
__device__ float g_accS[ND2], g_accQ[ND2];
// conv weights rearranged: [lk 0..9][h 0..1][ci 0..63][tap 0..8][co32]
__device__ float g_wP[10*2*64*9*32];

__device__ __forceinline__ float lrelu(float v){ return fmaxf(v, 0.01f*v); }

__device__ __forceinline__ float wsum(float v){
  #pragma unroll
  for(int o=16;o>0;o>>=1) v += __shfl_down_sync(0xffffffffu, v, o);
  return v;
}

// ---------------- small kernels ----------------
__global__ void k_zero(){
  int t = threadIdx.x;
  if(t < ND2){ g_accS[t]=0.f; g_accQ[t]=0.f; }
}

// rearrange conv weights: rw layout [lk][co][ci][ky][kx] -> [lk][h][ci][tap][co32]
__global__ void k_prepW(const float* __restrict__ rw){
  int idx = blockIdx.x*256 + threadIdx.x;
  if(idx >= 10*2*64*9*32) return;
  int c32 = idx & 31;
  int tap = (idx>>5) % 9;
  int ci  = (idx/(32*9)) % 64;
  int h   = (idx/(32*9*64)) & 1;
  int lk  = idx/(32*9*64*2);
  g_wP[idx] = rw[ ((lk*CH + h*32 + c32)*CH + ci)*9 + tap ];
}

__global__ void k_stats1d(const float* __restrict__ x1){
  int d = blockIdx.x;
  const float* p = x1 + d*LDIM;
  float s=0.f,q=0.f;
  for(int i=threadIdx.x;i<LDIM;i+=128){ float v=p[i]; s+=v; q+=v*v; }
  __shared__ float ss[4], sq[4];
  s = wsum(s); q = wsum(q);
  int w = threadIdx.x>>5, ln = threadIdx.x&31;
  if(ln==0){ ss[w]=s; sq[w]=q; }
  __syncthreads();
  if(threadIdx.x==0){
    float S=ss[0]+ss[1]+ss[2]+ss[3], Q=sq[0]+sq[1]+sq[2]+sq[3];
    float mu=S/(float)LDIM; float var=Q/(float)LDIM-mu*mu;
    g_rs1[d]=rsqrtf(var+EPSV);
  }
}

__global__ void k_stats2(const float* __restrict__ x2){
  int d = blockIdx.x, seg = blockIdx.y;
  const float* p = x2 + d*NHW + seg*36864;
  float s=0.f,q=0.f;
  for(int i=threadIdx.x;i<36864;i+=256){ float v=p[i]; s+=v; q+=v*v; }
  __shared__ float ss[8], sq[8];
  s=wsum(s); q=wsum(q);
  int w=threadIdx.x>>5, ln=threadIdx.x&31;
  if(ln==0){ ss[w]=s; sq[w]=q; }
  __syncthreads();
  if(threadIdx.x==0){
    float S=0.f,Q=0.f;
    #pragma unroll
    for(int i=0;i<8;i++){S+=ss[i];Q+=sq[i];}
    atomicAdd(&g_accS[d],S); atomicAdd(&g_accQ[d],Q);
  }
}

__global__ void k_fin_rs2(){
  int t=threadIdx.x;
  if(t<ND2){
    float mu = g_accS[t]/(float)NHW;
    float var = g_accQ[t]/(float)NHW - mu*mu;
    g_rs2[t] = rsqrtf(var+EPSV);
  }
}

__global__ void k_foldW1(const float* __restrict__ W1){
  int idx = blockIdx.x*256+threadIdx.x;
  if(idx < CH*ND1){
    int c = idx/ND1, d = idx%ND1;
    float rs = g_rs1[d];
    g_W1af[idx] = W1[c*2*ND1 + d]*rs;
    g_W1bf[idx] = W1[c*2*ND1 + ND1 + d]*rs;
  }
}

__global__ void k_foldW2(const float* __restrict__ W2){
  int idx = blockIdx.x*256+threadIdx.x;
  if(idx < CH*ND2) g_W2f[idx] = W2[idx]*g_rs2[idx%ND2];
}

__global__ void k_rowcol(const float* __restrict__ x1){
  int c = blockIdx.x, i = threadIdx.x;
  const float* wa = g_W1af + c*ND1;
  const float* wb = g_W1bf + c*ND1;
  float r=0.f, cl=0.f;
  for(int d=0; d<ND1; d++){
    float v = x1[d*LDIM + i];
    r  += wa[d]*v;
    cl += wb[d]*v;
  }
  g_row[c*LDIM+i]=r; g_col[c*LDIM+i]=cl;
}

__global__ void k_rcstats(const float* __restrict__ g1, const float* __restrict__ b1){
  int c = blockIdx.x;
  float sr=0.f,qr=0.f,sc=0.f,qc=0.f;
  for(int i=threadIdx.x;i<LDIM;i+=128){
    float r=g_row[c*LDIM+i], cl=g_col[c*LDIM+i];
    sr+=r; qr+=r*r; sc+=cl; qc+=cl*cl;
  }
  __shared__ float sm4[4][4];
  sr=wsum(sr); qr=wsum(qr); sc=wsum(sc); qc=wsum(qc);
  int w=threadIdx.x>>5, ln=threadIdx.x&31;
  if(ln==0){ sm4[w][0]=sr; sm4[w][1]=qr; sm4[w][2]=sc; sm4[w][3]=qc; }
  __syncthreads();
  if(threadIdx.x==0){
    float Sr=0.f,Qr=0.f,Sc=0.f,Qc=0.f;
    #pragma unroll
    for(int i=0;i<4;i++){Sr+=sm4[i][0];Qr+=sm4[i][1];Sc+=sm4[i][2];Qc+=sm4[i][3];}
    float mr=Sr/(float)LDIM, mc=Sc/(float)LDIM;
    float vr=Qr/(float)LDIM-mr*mr, vc=Qc/(float)LDIM-mc*mc;
    float rs=rsqrtf(vr+vc+EPSV);
    float a=g1[c]*rs;
    g_a1[c]=a; g_c1[c]=b1[c]-(mr+mc)*a;
  }
}

// pair2 GEMM with packed f32x2: y2[c,p] = sum_d W2f[c,d]*x2[d,p]
// block: 256 px (2 per thread), cg (tid>>7) handles 32 co.
__global__ void k_pair2(const float* __restrict__ x2){
  extern __shared__ float sm[];
  float* W2T = sm;            // [d][c] 210*64
  float* xs  = sm + 13440;    // 6*256
  int tid=threadIdx.x;
  for(int i=tid;i<13440;i+=256){ int d=i>>6, c=i&63; W2T[i]=g_W2f[c*ND2+d]; }
  int cg = tid>>7, pxl = tid&127;
  int pix0 = blockIdx.x*256;
  unsigned long long a0[16], a1[16];
  #pragma unroll
  for(int p=0;p<16;p++){ a0[p]=0ULL; a1[p]=0ULL; }
  __syncthreads();
  for(int d0=0; d0<ND2; d0+=6){
    for(int i=tid;i<1536;i+=256) xs[i] = x2[(d0 + (i>>8))*NHW + pix0 + (i&255)];
    __syncthreads();
    #pragma unroll
    for(int dd=0;dd<6;dd++){
      float2 v = *(const float2*)(xs + dd*256 + pxl*2);
      unsigned long long dv0, dv1;
      asm("mov.b64 %0, {%1,%1};" : "=l"(dv0) : "f"(v.x));
      asm("mov.b64 %0, {%1,%1};" : "=l"(dv1) : "f"(v.y));
      const unsigned long long* wp = (const unsigned long long*)(W2T + (d0+dd)*64 + cg*32);
      #pragma unroll
      for(int p=0;p<16;p++){
        unsigned long long w2 = wp[p];
        asm("fma.rn.f32x2 %0, %1, %2, %0;" : "+l"(a0[p]) : "l"(w2), "l"(dv0));
        asm("fma.rn.f32x2 %0, %1, %2, %0;" : "+l"(a1[p]) : "l"(w2), "l"(dv1));
      }
    }
    __syncthreads();
  }
  int P = pix0 + pxl*2;
  #pragma unroll
  for(int p=0;p<16;p++){
    float l0,h0,l1,h1;
    asm("mov.b64 {%0,%1}, %2;" : "=f"(l0), "=f"(h0) : "l"(a0[p]));
    asm("mov.b64 {%0,%1}, %2;" : "=f"(l1), "=f"(h1) : "l"(a1[p]));
    int c = cg*32 + 2*p;
    g_bufU[c*NHW + P]       = l0;
    g_bufU[c*NHW + P + 1]   = l1;
    g_bufU[(c+1)*NHW + P]   = h0;
    g_bufU[(c+1)*NHW + P+1] = h1;
  }
}

// pair stage: p1 act (separable) + p2 act, then 64x128 channel mix into bufX
__global__ void k_pair(const float* __restrict__ W3){
  extern __shared__ float sm[];
  float* Wa  = sm;            // 64*64
  float* Wb  = sm+4096;       // 64*64
  float* p1s = sm+8192;       // 64*32
  float* p2s = sm+8192+2048;  // 64*32
  int tid=threadIdx.x;
  for(int i=tid;i<4096;i+=256){
    int c=i>>6, d=i&63;
    Wa[i]=W3[c*128+d]; Wb[i]=W3[c*128+64+d];
  }
  int px=tid&31, cg=tid>>5;
  int P = blockIdx.x*32 + px;
  int i = P/LDIM, j = P - i*LDIM;
  __syncthreads();
  #pragma unroll
  for(int r=0;r<8;r++){
    int c=cg*8+r;
    float v1 = g_row[c*LDIM+i] + g_col[c*LDIM+j];
    p1s[c*32+px] = lrelu(g_a1[c]*v1 + g_c1[c]);
    float u = g_bufU[c*NHW + P];
    p2s[c*32+px] = lrelu(g_a2[c]*u + g_c2[c]);
  }
  __syncthreads();
  float acc[8];
  #pragma unroll
  for(int r=0;r<8;r++) acc[r]=0.f;
  for(int dd=0;dd<64;dd++){
    float v1=p1s[dd*32+px], v2=p2s[dd*32+px];
    #pragma unroll
    for(int r=0;r<8;r++){
      int c=cg*8+r;
      acc[r] += Wa[c*64+dd]*v1 + Wb[c*64+dd]*v2;
    }
  }
  #pragma unroll
  for(int r=0;r<8;r++) g_bufX[(cg*8+r)*NHW + P] = acc[r];
}

__global__ void k_cstats(const float* __restrict__ buf){
  int c=blockIdx.x, seg=blockIdx.y;
  const float* p = buf + c*NHW + seg*18432;
  float s=0.f,q=0.f;
  for(int i=threadIdx.x;i<18432;i+=256){ float v=p[i]; s+=v; q+=v*v; }
  __shared__ float ss[8], sq[8];
  s=wsum(s); q=wsum(q);
  int w=threadIdx.x>>5, ln=threadIdx.x&31;
  if(ln==0){ ss[w]=s; sq[w]=q; }
  __syncthreads();
  if(threadIdx.x==0){
    float S=0.f,Q=0.f;
    #pragma unroll
    for(int i=0;i<8;i++){S+=ss[i];Q+=sq[i];}
    atomicAdd(&g_accS[c],S); atomicAdd(&g_accQ[c],Q);
  }
}

__global__ void k_fin_affine(const float* __restrict__ gamma, const float* __restrict__ beta,
                             float* __restrict__ aOut, float* __restrict__ cOut){
  int t=threadIdx.x;
  if(t<CH){
    float mu = g_accS[t]/(float)NHW;
    float var = g_accQ[t]/(float)NHW - mu*mu;
    float rs = rsqrtf(var+EPSV);
    float a = gamma[t]*rs;
    aOut[t]=a; cOut[t]=beta[t]-mu*a;
  }
}

__global__ void k_apply(float* __restrict__ buf){
  int c=blockIdx.y;
  int idx=c*NHW + blockIdx.x*256 + threadIdx.x;
  buf[idx] = lrelu(g_aG[c]*buf[idx]+g_cG[c]);
}

__global__ void k_apply_res(const float* __restrict__ u, const float* __restrict__ res,
                            float* __restrict__ o){
  int c=blockIdx.y;
  int idx=c*NHW + blockIdx.x*256 + threadIdx.x;
  o[idx] = lrelu(g_aG[c]*u[idx]+g_cG[c]) + res[idx];
}

// ---------------- conv 3x3 dilated 64->64, packed f32x2, co-split ----------------
// CTA: 32x16 px tile (2 px/thread: rows ty and ty+8), 32 co (blockIdx.z half).
// Weights: [ci][tap][co32] in SMEM (73.7KB) -> 2 CTAs/SM.
// Optional fused input activation (affine+lrelu) during staging.
template<int D>
__global__ void __launch_bounds__(256,2)
k_conv2(const float* __restrict__ in, float* __restrict__ out,
        const float* __restrict__ wP,
        const float* __restrict__ aAff, const float* __restrict__ cAff){
  constexpr int TW = 32+2*D, TH = 16+2*D, PLSZ = TW*TH;
  extern __shared__ float sm[];
  float* ws   = sm;               // 64*9*32 = 18432 floats
  float* tile = sm + 18432;       // 8*PLSZ
  float* aS   = tile + 8*PLSZ;    // 64
  float* cS   = aS + 64;          // 64
  int tid = threadIdx.x;
  int h = blockIdx.z;

  // stage weights for this co-half (coalesced float4)
  {
    const float4* wg = (const float4*)(wP + h*18432);
    float4* ws4 = (float4*)ws;
    for(int i=tid;i<4608;i+=256) ws4[i]=wg[i];
  }
  bool doAct = (aAff != nullptr);
  if(tid<64){ aS[tid] = doAct ? aAff[tid] : 1.f; cS[tid] = doAct ? cAff[tid] : 0.f; }

  int x = tid&31, ty = tid>>5;
  int x0 = blockIdx.x*32, y0 = blockIdx.y*16;

  unsigned long long a0[16], a1[16];
  #pragma unroll
  for(int p=0;p<16;p++){ a0[p]=0ULL; a1[p]=0ULL; }

  for(int c0=0;c0<64;c0+=8){
    __syncthreads();  // weights/act ready (1st) + previous tile consumed
    for(int i=tid;i<8*PLSZ;i+=256){
      int cc = i/PLSZ, rr = i - cc*PLSZ;
      int row = rr/TW, col = rr - row*TW;
      int gy = y0 + row - D, gx = x0 + col - D;
      float v = 0.f;
      if(gy>=0 && gy<LDIM && gx>=0 && gx<LDIM){
        float xv = in[(c0+cc)*NHW + gy*LDIM + gx];
        if(doAct){ float t = aS[c0+cc]*xv + cS[c0+cc]; v = fmaxf(t, 0.01f*t); }
        else v = xv;
      }
      tile[i] = v;
    }
    __syncthreads();
    #pragma unroll
    for(int cc=0;cc<8;cc++){
      int ci = c0+cc;
      const float* tp = tile + cc*PLSZ + ty*TW + x;
      #pragma unroll
      for(int kk=0;kk<9;kk++){
        int ky=kk/3, kx=kk-ky*3;
        float v0 = tp[ky*D*TW + kx*D];
        float v1 = tp[(ky*D+8)*TW + kx*D];
        unsigned long long dv0, dv1;
        asm("mov.b64 %0, {%1,%1};" : "=l"(dv0) : "f"(v0));
        asm("mov.b64 %0, {%1,%1};" : "=l"(dv1) : "f"(v1));
        const ulonglong2* wk = ((const ulonglong2*)ws) + (ci*9+kk)*8;
        #pragma unroll
        for(int p=0;p<8;p++){
          ulonglong2 w2 = wk[p];
          asm("fma.rn.f32x2 %0, %1, %2, %0;" : "+l"(a0[2*p  ]) : "l"(w2.x), "l"(dv0));
          asm("fma.rn.f32x2 %0, %1, %2, %0;" : "+l"(a0[2*p+1]) : "l"(w2.y), "l"(dv0));
          asm("fma.rn.f32x2 %0, %1, %2, %0;" : "+l"(a1[2*p  ]) : "l"(w2.x), "l"(dv1));
          asm("fma.rn.f32x2 %0, %1, %2, %0;" : "+l"(a1[2*p+1]) : "l"(w2.y), "l"(dv1));
        }
      }
    }
  }
  // epilogue: a0 -> row ty, a1 -> row ty+8; co pairs (4 per ulonglong2-load pattern)
  int gy = y0+ty, gx = x0+x;
  float* op = out + (h*32)*NHW + gy*LDIM + gx;
  #pragma unroll
  for(int p=0;p<16;p++){
    float l0,h0,l1,h1;
    asm("mov.b64 {%0,%1}, %2;" : "=f"(l0), "=f"(h0) : "l"(a0[p]));
    asm("mov.b64 {%0,%1}, %2;" : "=f"(l1), "=f"(h1) : "l"(a1[p]));
    op[(2*p  )*NHW]            = l0;
    op[(2*p+1)*NHW]            = h0;
    op[(2*p  )*NHW + 8*LDIM]   = l1;
    op[(2*p+1)*NHW + 8*LDIM]   = h1;
  }
}

// ---------------- host ----------------
static void launch_conv(int d, const float* in, float* out, const float* w,
                        const float* aA, const float* cA){
  dim3 g(12,24,2);
  if(d==1)      k_conv2<1><<<g,256,93824>>>(in,out,w,aA,cA);
  else if(d==2) k_conv2<2><<<g,256,97280>>>(in,out,w,aA,cA);
  else          k_conv2<4><<<g,256,104960>>>(in,out,w,aA,cA);
}

extern "C" void kernel_launch(void* const* d_in, const int* in_sizes, int n_in,
                              void* d_out, int out_size){
  const float* x1 =(const float*)d_in[0];
  const float* x2 =(const float*)d_in[1];
  const float* W1 =(const float*)d_in[2];
  const float* g1 =(const float*)d_in[3];
  const float* b1 =(const float*)d_in[4];
  const float* W2 =(const float*)d_in[5];
  const float* g2 =(const float*)d_in[6];
  const float* b2 =(const float*)d_in[7];
  const float* W3 =(const float*)d_in[8];
  const float* g3 =(const float*)d_in[9];
  const float* b3 =(const float*)d_in[10];
  const float* rw =(const float*)d_in[11];
  const float* rg =(const float*)d_in[13];
  const float* rbe=(const float*)d_in[14];
  float* outp=(float*)d_out;

  float *bufT,*bufU,*bufX,*wP,*a2p,*c2p,*aGp,*cGp;
  cudaGetSymbolAddress((void**)&bufT, g_bufT);
  cudaGetSymbolAddress((void**)&bufU, g_bufU);
  cudaGetSymbolAddress((void**)&bufX, g_bufX);
  cudaGetSymbolAddress((void**)&wP,   g_wP);
  cudaGetSymbolAddress((void**)&a2p,  g_a2);
  cudaGetSymbolAddress((void**)&c2p,  g_c2);
  cudaGetSymbolAddress((void**)&aGp,  g_aG);
  cudaGetSymbolAddress((void**)&cGp,  g_cG);

  cudaFuncSetAttribute(k_conv2<1>, cudaFuncAttributeMaxDynamicSharedMemorySize, 93824);
  cudaFuncSetAttribute(k_conv2<2>, cudaFuncAttributeMaxDynamicSharedMemorySize, 97280);
  cudaFuncSetAttribute(k_conv2<4>, cudaFuncAttributeMaxDynamicSharedMemorySize, 104960);
  cudaFuncSetAttribute(k_pair2,    cudaFuncAttributeMaxDynamicSharedMemorySize, 61440);
  cudaFuncSetAttribute(k_pair,     cudaFuncAttributeMaxDynamicSharedMemorySize, 49152);

  k_prepW<<<1440,256>>>(rw);
  k_zero<<<1,256>>>();
  k_stats1d<<<788,128>>>(x1);
  k_stats2<<<dim3(210,4),256>>>(x2);
  k_fin_rs2<<<1,256>>>();
  k_foldW1<<<(CH*ND1+255)/256,256>>>(W1);
  k_foldW2<<<(CH*ND2+255)/256,256>>>(W2);
  k_rowcol<<<64,384>>>(x1);
  k_rcstats<<<64,128>>>(g1,b1);
  k_pair2<<<576,256,61440>>>(x2);
  k_zero<<<1,256>>>();
  k_cstats<<<dim3(64,8),256>>>(bufU);
  k_fin_affine<<<1,64>>>(g2,b2,a2p,c2p);
  k_pair<<<4608,256,49152>>>(W3);
  k_zero<<<1,256>>>();
  k_cstats<<<dim3(64,8),256>>>(bufX);
  k_fin_affine<<<1,64>>>(g3,b3,aGp,cGp);
  k_apply<<<dim3(576,64),256>>>(bufX);   // bufX = activated pair output (residual)

  const int dil[5]={1,2,4,2,1};
  for(int l=0;l<5;l++){
    int d=dil[l];
    const float* w0 = wP + (l*2  )*2*18432;
    const float* w1 = wP + (l*2+1)*2*18432;
    // conv1: input already activated
    launch_conv(d, bufX, bufT, w0, nullptr, nullptr);
    k_zero<<<1,256>>>();
    k_cstats<<<dim3(64,8),256>>>(bufT);
    k_fin_affine<<<1,64>>>(rg + (l*2)*CH, rbe + (l*2)*CH, aGp, cGp);
    // conv2: affine+lrelu fused into input staging
    launch_conv(d, bufT, bufU, w1, aGp, cGp);
    k_zero<<<1,256>>>();
    k_cstats<<<dim3(64,8),256>>>(bufU);
    k_fin_affine<<<1,64>>>(rg + (l*2+1)*CH, rbe + (l*2+1)*CH, aGp, cGp);
    k_apply_res<<<dim3(576,64),256>>>(bufU, bufX, (l==4)? outp : bufX);
  }
}